// round 1
// baseline (speedup 1.0000x reference)
#include <cuda_runtime.h>
#include <cuda_bf16.h>

// Problem constants (fixed by the reference setup_inputs)
constexpr int T_STEPS = 2048;
constexpr int BATCH   = 8192;
constexpr int UNROLL  = 16;   // float4 loads in flight per thread (double-buffered)
constexpr int TPB     = 64;   // 128 blocks -> ~1 block per SM

// Izhikevich params (regular spiking)
#define IZH_A   0.02f
#define IZH_B   0.2f
#define IZH_C   (-65.0f)
#define IZH_D   8.0f
#define IZH_VTH 30.0f

// One Euler step, matching the reference op order exactly:
//   v = v + (0.04*v*v + 5*v + 140 - u + I)
//   u = u + A*(B*v - u)        (uses updated v, pre-reset)
//   z = (v >= 30) ? 1 : 0
//   v = z ? C : v
//   u = u + z*D
__device__ __forceinline__ float izh_step(float& v, float& u, float I) {
    v = v + (0.04f * v * v + 5.0f * v + 140.0f - u + I);
    u = u + IZH_A * (IZH_B * v - u);
    float z = (v >= IZH_VTH) ? 1.0f : 0.0f;
    v = (z > 0.0f) ? IZH_C : v;
    u = u + z * IZH_D;
    return z;
}

__global__ __launch_bounds__(TPB) void snn_izh_kernel(
    const float4* __restrict__ xs,     // [T, B] of float4 (F_IN=4)
    const float*  __restrict__ W_in,   // [2,4]
    const float*  __restrict__ b_in,   // [2]
    const float*  __restrict__ W_out,  // [1,2]
    const float*  __restrict__ b_out,  // [1]
    float*        __restrict__ out)    // [T, B]
{
    const int b = blockIdx.x * TPB + threadIdx.x;
    if (b >= BATCH) return;

    // Broadcast weight loads (uniform across warp -> constant-like)
    const float w00 = W_in[0], w01 = W_in[1], w02 = W_in[2], w03 = W_in[3];
    const float w10 = W_in[4], w11 = W_in[5], w12 = W_in[6], w13 = W_in[7];
    const float bi0 = b_in[0], bi1 = b_in[1];
    const float wo0 = W_out[0], wo1 = W_out[1];
    const float bo  = b_out[0];

    // Neuron states: two hidden + one output
    float v0 = IZH_C, u0 = IZH_B * IZH_C;
    float v1 = IZH_C, u1 = IZH_B * IZH_C;
    float v2 = IZH_C, u2 = IZH_B * IZH_C;

    // Double-buffered software pipeline over T in chunks of UNROLL
    float4 bufA[UNROLL];
    float4 bufB[UNROLL];

    const float4* xsb = xs + b;   // stride BATCH between timesteps
    float* outb = out + b;

    #pragma unroll
    for (int k = 0; k < UNROLL; k++)
        bufA[k] = xsb[(size_t)k * BATCH];

    constexpr int NCHUNK = T_STEPS / UNROLL;
    #pragma unroll 1
    for (int c = 0; c < NCHUNK; c++) {
        // Issue next chunk's loads before computing the current one
        const int nbase = (c + 1) * UNROLL;
        if (c + 1 < NCHUNK) {
            #pragma unroll
            for (int k = 0; k < UNROLL; k++)
                bufB[k] = xsb[(size_t)(nbase + k) * BATCH];
        }

        const int tbase = c * UNROLL;
        #pragma unroll
        for (int k = 0; k < UNROLL; k++) {
            const float4 x = bufA[k];

            // input linear: h = xs @ W_in^T + b_in
            float h0 = w00 * x.x + w01 * x.y + w02 * x.z + w03 * x.w + bi0;
            float h1 = w10 * x.x + w11 * x.y + w12 * x.z + w13 * x.w + bi1;

            // hidden Izhikevich neurons (independent -> parallel chains)
            float z0 = izh_step(v0, u0, h0);
            float z1 = izh_step(v1, u1, h1);

            // output linear on spikes, then output neuron
            float y = wo0 * z0 + wo1 * z1 + bo;
            float z2 = izh_step(v2, u2, y);

            outb[(size_t)(tbase + k) * BATCH] = z2;
        }

        // swap buffers
        #pragma unroll
        for (int k = 0; k < UNROLL; k++)
            bufA[k] = bufB[k];
    }
}

extern "C" void kernel_launch(void* const* d_in, const int* in_sizes, int n_in,
                              void* d_out, int out_size) {
    const float4* xs    = (const float4*)d_in[0];
    const float*  W_in  = (const float*)d_in[1];
    const float*  b_in  = (const float*)d_in[2];
    const float*  W_out = (const float*)d_in[3];
    const float*  b_out = (const float*)d_in[4];
    float* out = (float*)d_out;

    dim3 grid(BATCH / TPB);
    dim3 block(TPB);
    snn_izh_kernel<<<grid, block>>>(xs, W_in, b_in, W_out, b_out, out);
}

// round 2
// speedup vs baseline: 1.3087x; 1.3087x over previous
#include <cuda_runtime.h>
#include <cuda_bf16.h>

// Problem constants (fixed by the reference setup_inputs)
constexpr int T_STEPS = 2048;
constexpr int BATCH   = 8192;
constexpr int UNROLL  = 16;                 // rolling prefetch depth (float4/thread)
constexpr int TPB     = 128;                // 4 warps/block -> 1 warp per SMSP
constexpr int NTHREADS = BATCH * 2;         // one thread per (batch, hidden-neuron)
constexpr int NCHUNK  = T_STEPS / UNROLL;

// Izhikevich params (regular spiking)
#define IZH_A   0.02f
#define IZH_B   0.2f
#define IZH_C   (-65.0f)
#define IZH_D   8.0f
#define IZH_VTH 30.0f

// EXACT expression order from the reference (verified rel_err == 0.0) — do not reorder.
__device__ __forceinline__ float izh_step(float& v, float& u, float I) {
    v = v + (0.04f * v * v + 5.0f * v + 140.0f - u + I);
    u = u + IZH_A * (IZH_B * v - u);
    float z = (v >= IZH_VTH) ? 1.0f : 0.0f;
    v = (z > 0.0f) ? IZH_C : v;
    u = u + z * IZH_D;
    return z;
}

__global__ __launch_bounds__(TPB) void snn_izh_pair_kernel(
    const float4* __restrict__ xs,     // [T, B] float4 (F_IN = 4)
    const float*  __restrict__ W_in,   // [2,4]
    const float*  __restrict__ b_in,   // [2]
    const float*  __restrict__ W_out,  // [1,2]
    const float*  __restrict__ b_out,  // [1]
    float*        __restrict__ out)    // [T, B]
{
    const int tid = blockIdx.x * TPB + threadIdx.x;
    const int b   = tid >> 1;          // batch element
    const int n   = tid & 1;           // hidden neuron index (0 or 1)
    const bool is0 = (n == 0);

    // Per-lane weights for the owned hidden neuron
    const float w0 = W_in[n * 4 + 0];
    const float w1 = W_in[n * 4 + 1];
    const float w2 = W_in[n * 4 + 2];
    const float w3 = W_in[n * 4 + 3];
    const float bi = b_in[n];
    const float wo0 = W_out[0], wo1 = W_out[1];
    const float bo  = b_out[0];

    // States: owned hidden neuron + (redundant on both lanes) output neuron
    float v  = IZH_C, u  = IZH_B * IZH_C;
    float v2 = IZH_C, u2 = IZH_B * IZH_C;

    const float4* xp = xs + b;         // stride BATCH between timesteps
    float* op = out + b;

    // Rolling prefetch buffer — consume buf[k], immediately refill with chunk c+1.
    float4 buf[UNROLL];
    #pragma unroll
    for (int k = 0; k < UNROLL; k++)
        buf[k] = xp[(size_t)k * BATCH];

    // Spikes from the previous timestep (neuron-2 lags one step to hide SHFL latency)
    float zps = 0.0f, zpo = 0.0f;

    // ---- chunk 0 (peeled: k==0 has no previous spikes -> skip neuron 2) ----
    #pragma unroll
    for (int k = 0; k < UNROLL; k++) {
        const float4 x = buf[k];
        buf[k] = xp[(size_t)(UNROLL + k) * BATCH];   // prefetch chunk 1

        const float h = w0 * x.x + w1 * x.y + w2 * x.z + w3 * x.w + bi;
        const float zs = izh_step(v, u, h);
        const float zo = __shfl_xor_sync(0xffffffffu, zs, 1);

        if (k > 0) {  // compile-time branch in the unrolled loop
            const float z0 = is0 ? zps : zpo;
            const float z1 = is0 ? zpo : zps;
            const float y  = z0 * wo0 + z1 * wo1 + bo;
            const float z2 = izh_step(v2, u2, y);
            if (is0) op[(size_t)(k - 1) * BATCH] = z2;
        }
        zps = zs; zpo = zo;
    }

    // ---- chunks 1 .. NCHUNK-2 (steady state: prefetch next chunk) ----
    #pragma unroll 1
    for (int c = 1; c < NCHUNK - 1; c++) {
        const int tbase = c * UNROLL;
        const int nbase = (c + 1) * UNROLL;
        #pragma unroll
        for (int k = 0; k < UNROLL; k++) {
            const float4 x = buf[k];
            buf[k] = xp[(size_t)(nbase + k) * BATCH];

            const float h = w0 * x.x + w1 * x.y + w2 * x.z + w3 * x.w + bi;
            const float zs = izh_step(v, u, h);
            const float zo = __shfl_xor_sync(0xffffffffu, zs, 1);

            const float z0 = is0 ? zps : zpo;
            const float z1 = is0 ? zpo : zps;
            const float y  = z0 * wo0 + z1 * wo1 + bo;
            const float z2 = izh_step(v2, u2, y);
            if (is0) op[(size_t)(tbase + k - 1) * BATCH] = z2;

            zps = zs; zpo = zo;
        }
    }

    // ---- last chunk (no prefetch) ----
    {
        const int tbase = (NCHUNK - 1) * UNROLL;
        #pragma unroll
        for (int k = 0; k < UNROLL; k++) {
            const float4 x = buf[k];

            const float h = w0 * x.x + w1 * x.y + w2 * x.z + w3 * x.w + bi;
            const float zs = izh_step(v, u, h);
            const float zo = __shfl_xor_sync(0xffffffffu, zs, 1);

            const float z0 = is0 ? zps : zpo;
            const float z1 = is0 ? zpo : zps;
            const float y  = z0 * wo0 + z1 * wo1 + bo;
            const float z2 = izh_step(v2, u2, y);
            if (is0) op[(size_t)(tbase + k - 1) * BATCH] = z2;

            zps = zs; zpo = zo;
        }
    }

    // ---- epilogue: output neuron for the final timestep ----
    {
        const float z0 = is0 ? zps : zpo;
        const float z1 = is0 ? zpo : zps;
        const float y  = z0 * wo0 + z1 * wo1 + bo;
        const float z2 = izh_step(v2, u2, y);
        if (is0) op[(size_t)(T_STEPS - 1) * BATCH] = z2;
    }
}

extern "C" void kernel_launch(void* const* d_in, const int* in_sizes, int n_in,
                              void* d_out, int out_size) {
    const float4* xs    = (const float4*)d_in[0];
    const float*  W_in  = (const float*)d_in[1];
    const float*  b_in  = (const float*)d_in[2];
    const float*  W_out = (const float*)d_in[3];
    const float*  b_out = (const float*)d_in[4];
    float* out = (float*)d_out;

    dim3 grid(NTHREADS / TPB);   // 128 blocks
    dim3 block(TPB);             // 128 threads
    snn_izh_pair_kernel<<<grid, block>>>(xs, W_in, b_in, W_out, b_out, out);
}

// round 3
// speedup vs baseline: 1.4696x; 1.1229x over previous
#include <cuda_runtime.h>
#include <cuda_bf16.h>

// Problem constants (fixed by the reference setup_inputs)
constexpr int T_STEPS = 2048;
constexpr int BATCH   = 8192;
constexpr int UNROLL  = 16;                 // steps per chunk (smem ring + prefetch depth)
constexpr int NCHUNK  = T_STEPS / UNROLL;   // 128
constexpr int EPB     = 32;                 // elements per block (one output warp)
constexpr int TPB     = 96;                 // warp0: hidden n0, warp1: hidden n1, warp2: output

// Izhikevich params (regular spiking)
#define IZH_A   0.02f
#define IZH_B   0.2f
#define IZH_C   (-65.0f)
#define IZH_D   8.0f
#define IZH_VTH 30.0f

__global__ __launch_bounds__(TPB) void snn_izh_ws_kernel(
    const float4* __restrict__ xs,     // [T, B] float4 (F_IN = 4)
    const float*  __restrict__ W_in,   // [2,4]
    const float*  __restrict__ b_in,   // [2]
    const float*  __restrict__ W_out,  // [1,2]
    const float*  __restrict__ b_out,  // [1]
    float*        __restrict__ out)    // [T, B]
{
    // Spike ring: [buf][step-in-chunk][neuron][element-lane]  (conflict-free STS/LDS)
    __shared__ float zbuf[2][UNROLL][2][EPB];

    const int wid  = threadIdx.x >> 5;
    const int lane = threadIdx.x & 31;
    const int elem = blockIdx.x * EPB + lane;

    if (wid < 2) {
        // ─────────── HIDDEN producer warp (one neuron per warp) ───────────
        const int n = wid;
        const float w0 = W_in[n * 4 + 0];
        const float w1 = W_in[n * 4 + 1];
        const float w2 = W_in[n * 4 + 2];
        const float w3 = W_in[n * 4 + 3];
        const float bi = b_in[n];

        float v = IZH_C, u = IZH_B * IZH_C;

        const float4* xp = xs + elem;           // stride BATCH between timesteps
        float4 buf[UNROLL];
        #pragma unroll
        for (int k = 0; k < UNROLL; k++)
            buf[k] = xp[(size_t)k * BATCH];

        #pragma unroll 1
        for (int c = 0; c <= NCHUNK; c++) {
            if (c < NCHUNK) {
                const int cb = c & 1;
                const int nbase = (c + 1) * UNROLL;
                #pragma unroll
                for (int k = 0; k < UNROLL; k++) {
                    const float4 x = buf[k];
                    if (c + 1 < NCHUNK)
                        buf[k] = xp[(size_t)(nbase + k) * BATCH];

                    // input linear (frozen expression order — bit-exact vs reference)
                    const float h = w0 * x.x + w1 * x.y + w2 * x.z + w3 * x.w + bi;

                    // Izhikevich step, single predicate
                    v = v + (0.04f * v * v + 5.0f * v + 140.0f - u + h);
                    u = u + IZH_A * (IZH_B * v - u);
                    const bool p = (v >= IZH_VTH);
                    const float z = p ? 1.0f : 0.0f;
                    v = p ? IZH_C : v;
                    u = p ? (u + IZH_D) : u;     // exact: fma(z,D,u) with z in {0,1}

                    zbuf[cb][k][n][lane] = z;
                }
            }
            __syncthreads();
        }
    } else {
        // ─────────── OUTPUT consumer warp (lags one chunk) ───────────
        const float wo0 = W_out[0], wo1 = W_out[1];
        const float bo  = b_out[0];

        float v = IZH_C, u = IZH_B * IZH_C;
        float* op = out + elem;

        #pragma unroll 1
        for (int c = 0; c <= NCHUNK; c++) {
            if (c > 0) {
                const int cb = (c - 1) & 1;
                const int tbase = (c - 1) * UNROLL;
                #pragma unroll
                for (int k = 0; k < UNROLL; k++) {
                    const float z0 = zbuf[cb][k][0][lane];
                    const float z1 = zbuf[cb][k][1][lane];

                    // output linear (frozen order)
                    const float y = z0 * wo0 + z1 * wo1 + bo;

                    v = v + (0.04f * v * v + 5.0f * v + 140.0f - u + y);
                    u = u + IZH_A * (IZH_B * v - u);
                    const bool p = (v >= IZH_VTH);
                    const float z2 = p ? 1.0f : 0.0f;
                    v = p ? IZH_C : v;
                    u = p ? (u + IZH_D) : u;

                    op[(size_t)(tbase + k) * BATCH] = z2;
                }
            }
            __syncthreads();
        }
    }
}

extern "C" void kernel_launch(void* const* d_in, const int* in_sizes, int n_in,
                              void* d_out, int out_size) {
    const float4* xs    = (const float4*)d_in[0];
    const float*  W_in  = (const float*)d_in[1];
    const float*  b_in  = (const float*)d_in[2];
    const float*  W_out = (const float*)d_in[3];
    const float*  b_out = (const float*)d_in[4];
    float* out = (float*)d_out;

    dim3 grid(BATCH / EPB);   // 256 blocks
    dim3 block(TPB);          // 96 threads: 2 hidden warps + 1 output warp
    snn_izh_ws_kernel<<<grid, block>>>(xs, W_in, b_in, W_out, b_out, out);
}